// round 12
// baseline (speedup 1.0000x reference)
#include <cuda_runtime.h>
#include <math.h>
#include <stdint.h>

// Problem constants
#define BB 2
#define NN 2048
#define BN 4096          // B*N
#define CC 256
#define HI 64
#define WI 176
#define HW (HI*WI)       // 11264
#define TS 16            // tile size
#define TBX (WI/TS)      // 11
#define TBY (HI/TS)      // 4
#define TPB (TBX*TBY)    // 44 tiles per batch
#define NT (BB*TPB)      // 88 tiles total
#define MAXG 2048
#define FM_SIZE (BB*CC*HW)

// ---------------- device scratch ----------------
__device__ float g_h1[BN*64];
__device__ float g_h2[BN*128];
__device__ float g_feats[BN*CC];
__device__ float g_ft1[BN*CC];
__device__ float g_featsT[BN*CC];

__device__ float g_px[BN], g_py[BN], g_isx[BN], g_isy[BN], g_w[BN], g_as[BN];
__device__ int   g_tcount[NT];
__device__ int   g_tlist[NT*MAXG];

// ---------------- tf32 helpers ----------------
__device__ __forceinline__ float f2tf32(float x) {
    uint32_t r; asm("cvt.rna.tf32.f32 %0, %1;" : "=r"(r) : "f"(x));
    return __uint_as_float(r);
}
__device__ __forceinline__ void mma_tf32(float* c,
    uint32_t a0, uint32_t a1, uint32_t a2, uint32_t a3,
    uint32_t b0, uint32_t b1)
{
    asm("mma.sync.aligned.m16n8k8.row.col.f32.tf32.tf32.f32 "
        "{%0,%1,%2,%3}, {%4,%5,%6,%7}, {%8,%9}, {%0,%1,%2,%3};"
        : "+f"(c[0]), "+f"(c[1]), "+f"(c[2]), "+f"(c[3])
        : "r"(a0), "r"(a1), "r"(a2), "r"(a3), "r"(b0), "r"(b1));
}

// ---------------- projection + binning (fused) ----------------
__global__ void proj_bin_kernel(const float* __restrict__ g, const float* __restrict__ Kin) {
    int i = blockIdx.x * blockDim.x + threadIdx.x;
    if (i >= BN) return;
    const float* gd = g + (size_t)i * 14;
    float x = gd[0], y = gd[1], z = gd[2];
    float k00 = Kin[0], k01 = Kin[1], k02 = Kin[2];
    float k10 = Kin[3], k11 = Kin[4], k12 = Kin[5];
    float k20 = Kin[6], k21 = Kin[7], k22 = Kin[8];
    float pz = k20 * x + k21 * y + k22 * z;
    float denom = pz + 1e-6f;
    float pxn = (k00 * x + k01 * y + k02 * z) / denom;
    float pyn = (k10 * x + k11 * y + k12 * z) / denom;
    float scale_x = (float)WI / k02 * 0.5f;
    float scale_y = (float)HI / k12 * 0.5f;
    float px = pxn * scale_x;
    float py = pyn * scale_y;
    bool valid = (z > 0.1f);
    bool inb = (px >= 0.f) && (px < (float)WI) && (py >= 0.f) && (py < (float)HI);
    bool mask = valid && inb;
    float sx = fmaxf(gd[5] * scale_x, 1.0f);
    float sy = fmaxf(gd[6] * scale_y, 1.0f);
    float w = mask ? gd[12] : 0.0f;
    g_px[i] = px;  g_py[i] = py;
    g_isx[i] = 1.0f / sx;  g_isy[i] = 1.0f / sy;
    g_w[i]  = w;
    g_as[i] = 0.5f * (sx + sy);
    if (w == 0.0f) return;

    float rx = 3.0f * sx;
    float ry = 3.0f * sy;
    int b = i >> 11;
    int tx0 = max(0, (int)floorf((px - rx) * (1.0f / TS)));
    int tx1 = min(TBX - 1, (int)floorf((px + rx) * (1.0f / TS)));
    int ty0 = max(0, (int)floorf((py - ry) * (1.0f / TS)));
    int ty1 = min(TBY - 1, (int)floorf((py + ry) * (1.0f / TS)));
    for (int ty = ty0; ty <= ty1; ty++)
        for (int tx = tx0; tx <= tx1; tx++) {
            int t = b * TPB + ty * TBX + tx;
            int o = atomicAdd(&g_tcount[t], 1);
            if (o < MAXG) g_tlist[t * MAXG + o] = i;
        }
}

// ---------------- tf32 GEMM: 64x64 tile, double-buffered, 3xTF32 ----------------
__global__ void __launch_bounds__(256) gemm_tf32_kernel(
    const float* __restrict__ A, const float* __restrict__ Wm,
    const float* __restrict__ bias, float* __restrict__ Cm,
    int Kd, int Nd, int doRelu)
{
    __shared__ float Ah[2][16][72], Al[2][16][72];
    __shared__ float Bh[2][16][72], Bl[2][16][72];

    int m0 = blockIdx.x * 64;
    int n0 = blockIdx.y * 64;
    int t = threadIdx.x;
    int lane = t & 31;
    int wid = t >> 5;
    int wm = wid & 1;
    int wn = wid >> 1;
    int g = lane >> 2;
    int c = lane & 3;

    float d[2][2][4];
    #pragma unroll
    for (int mt = 0; mt < 2; mt++)
        #pragma unroll
        for (int nt = 0; nt < 2; nt++)
            #pragma unroll
            for (int i = 0; i < 4; i++) d[mt][nt][i] = 0.f;

    int nkt = (Kd + 15) >> 4;
    bool fast = ((Kd & 15) == 0);

    int arow = t >> 2, ak0 = (t & 3) * 4;
    int bkk = t >> 4, bn4 = (t & 15) * 4;

    float av[4], bv[4];
    if (fast) {
        float4 q = *(const float4*)&A[(size_t)(m0 + arow) * Kd + ak0];
        av[0]=q.x; av[1]=q.y; av[2]=q.z; av[3]=q.w;
        float4 w = *(const float4*)&Wm[(size_t)bkk * Nd + n0 + bn4];
        bv[0]=w.x; bv[1]=w.y; bv[2]=w.z; bv[3]=w.w;
    } else {
        #pragma unroll
        for (int i = 0; i < 4; i++)
            av[i] = (ak0 + i < Kd) ? A[(size_t)(m0 + arow) * Kd + ak0 + i] : 0.f;
        bool ok = (bkk < Kd);
        #pragma unroll
        for (int i = 0; i < 4; i++)
            bv[i] = ok ? Wm[(size_t)bkk * Nd + n0 + bn4 + i] : 0.f;
    }

    for (int kt = 0; kt < nkt; kt++) {
        int buf = kt & 1;
        #pragma unroll
        for (int i = 0; i < 4; i++) {
            float hi = f2tf32(av[i]);
            Ah[buf][ak0 + i][arow] = hi;
            Al[buf][ak0 + i][arow] = f2tf32(av[i] - hi);
        }
        #pragma unroll
        for (int i = 0; i < 4; i++) {
            float hi = f2tf32(bv[i]);
            Bh[buf][bkk][bn4 + i] = hi;
            Bl[buf][bkk][bn4 + i] = f2tf32(bv[i] - hi);
        }
        __syncthreads();
        if (kt + 1 < nkt) {
            int kb = (kt + 1) * 16;
            if (fast) {
                float4 q = *(const float4*)&A[(size_t)(m0 + arow) * Kd + kb + ak0];
                av[0]=q.x; av[1]=q.y; av[2]=q.z; av[3]=q.w;
                float4 w = *(const float4*)&Wm[(size_t)(kb + bkk) * Nd + n0 + bn4];
                bv[0]=w.x; bv[1]=w.y; bv[2]=w.z; bv[3]=w.w;
            } else {
                #pragma unroll
                for (int i = 0; i < 4; i++)
                    av[i] = (kb + ak0 + i < Kd) ? A[(size_t)(m0 + arow) * Kd + kb + ak0 + i] : 0.f;
                bool ok = (kb + bkk < Kd);
                #pragma unroll
                for (int i = 0; i < 4; i++)
                    bv[i] = ok ? Wm[(size_t)(kb + bkk) * Nd + n0 + bn4 + i] : 0.f;
            }
        }
        #pragma unroll
        for (int ks = 0; ks < 2; ks++) {
            int kk = ks * 8;
            uint32_t ah[2][4], al[2][4], bh[2][2], bl[2][2];
            #pragma unroll
            for (int mt = 0; mt < 2; mt++) {
                int m = wm * 32 + mt * 16 + g;
                ah[mt][0] = __float_as_uint(Ah[buf][kk + c][m]);
                ah[mt][1] = __float_as_uint(Ah[buf][kk + c][m + 8]);
                ah[mt][2] = __float_as_uint(Ah[buf][kk + c + 4][m]);
                ah[mt][3] = __float_as_uint(Ah[buf][kk + c + 4][m + 8]);
                al[mt][0] = __float_as_uint(Al[buf][kk + c][m]);
                al[mt][1] = __float_as_uint(Al[buf][kk + c][m + 8]);
                al[mt][2] = __float_as_uint(Al[buf][kk + c + 4][m]);
                al[mt][3] = __float_as_uint(Al[buf][kk + c + 4][m + 8]);
            }
            #pragma unroll
            for (int nt = 0; nt < 2; nt++) {
                int n = wn * 16 + nt * 8 + g;
                bh[nt][0] = __float_as_uint(Bh[buf][kk + c][n]);
                bh[nt][1] = __float_as_uint(Bh[buf][kk + c + 4][n]);
                bl[nt][0] = __float_as_uint(Bl[buf][kk + c][n]);
                bl[nt][1] = __float_as_uint(Bl[buf][kk + c + 4][n]);
            }
            #pragma unroll
            for (int mt = 0; mt < 2; mt++)
                #pragma unroll
                for (int nt = 0; nt < 2; nt++) {
                    mma_tf32(d[mt][nt], ah[mt][0], ah[mt][1], ah[mt][2], ah[mt][3],
                             bh[nt][0], bh[nt][1]);
                    mma_tf32(d[mt][nt], al[mt][0], al[mt][1], al[mt][2], al[mt][3],
                             bh[nt][0], bh[nt][1]);
                    mma_tf32(d[mt][nt], ah[mt][0], ah[mt][1], ah[mt][2], ah[mt][3],
                             bl[nt][0], bl[nt][1]);
                }
        }
    }

    #pragma unroll
    for (int nt = 0; nt < 2; nt++) {
        int col = n0 + wn * 16 + nt * 8 + c * 2;
        float2 bv2 = *(const float2*)&bias[col];
        #pragma unroll
        for (int mt = 0; mt < 2; mt++) {
            int row0 = m0 + wm * 32 + mt * 16 + g;
            float2 o0 = make_float2(d[mt][nt][0] + bv2.x, d[mt][nt][1] + bv2.y);
            float2 o1 = make_float2(d[mt][nt][2] + bv2.x, d[mt][nt][3] + bv2.y);
            if (doRelu) {
                o0.x = fmaxf(o0.x, 0.f); o0.y = fmaxf(o0.y, 0.f);
                o1.x = fmaxf(o1.x, 0.f); o1.y = fmaxf(o1.y, 0.f);
            }
            *(float2*)&Cm[(size_t)row0 * Nd + col]       = o0;
            *(float2*)&Cm[(size_t)(row0 + 8) * Nd + col] = o1;
        }
    }
}

// ---------------- tile render: 2 slices x 128 ch, tensor-core accumulate ------
// grid (NT, 2), 256 threads = 8 warps in 2(ch: 64 each) x 4(px: 64 each).
// F kept hi/lo (2xTF32); gw single tf32 (density/uncertainty exact fp32).
__global__ void __launch_bounds__(256) render_kernel(float* __restrict__ out) {
    int tile = blockIdx.x;
    int slice = blockIdx.y;
    int b = tile / TPB;
    int tl = tile % TPB;
    int tx0 = (tl % TBX) * TS;
    int ty0 = (tl / TBX) * TS;
    int t = threadIdx.x;
    int lx = t & 15;
    int ly = t >> 4;
    int lane = t & 31;
    int wid = t >> 5;
    int wm = wid & 1;        // 2 warps in channels (64 each)
    int wn = wid >> 1;       // 4 warps in pixels (64 each)
    int g = lane >> 2;
    int c = lane & 3;

    __shared__ float s_px[16], s_py[16], s_isx[16], s_isy[16], s_w[16], s_as[16];
    __shared__ int   s_n[16];
    __shared__ float s_dx2[16][16], s_dy2[16][16], s_ex[16][16], s_ey[16][16];
    __shared__ float s_gwh[16][264];             // gw tf32-hi, stride 264
    __shared__ float s_Fh[16][136], s_Fl[16][136];  // 128 ch + pad

    float* s_d = &s_dx2[0][0];   // reused for density after main loop

    float d[4][8][4];   // 4 mt (64 ch) x 8 nt (64 px) x frag
    #pragma unroll
    for (int mt = 0; mt < 4; mt++)
        #pragma unroll
        for (int nt = 0; nt < 8; nt++)
            #pragma unroll
            for (int i = 0; i < 4; i++) d[mt][nt][i] = 0.f;
    float dacc = 0.f, uacc = 0.f;

    int K = g_tcount[tile];
    if (K > MAXG) K = MAXG;

    for (int c0 = 0; c0 < K; c0 += 16) {
        if (t < 16) {
            int idx = c0 + t;
            if (idx < K) {
                int n = g_tlist[tile * MAXG + idx];
                s_n[t] = n;
                s_px[t] = g_px[n];   s_py[t] = g_py[n];
                s_isx[t] = g_isx[n]; s_isy[t] = g_isy[n];
                s_w[t] = g_w[n];     s_as[t] = g_as[n];
            } else {
                s_n[t] = 0;
                s_px[t] = 3e8f; s_py[t] = 3e8f;
                s_isx[t] = 1.f; s_isy[t] = 1.f;
                s_w[t] = 0.f;   s_as[t] = 0.f;
            }
        }
        __syncthreads();
        // F slice: 16 gaussians x 128 channels, hi/lo (two float4 per thread)
        {
            int j = t >> 4;
            int ci = (t & 15) * 8;
            int n = s_n[j];
            const float* fp = &g_featsT[(size_t)n * CC + slice * 128 + ci];
            float4 f0 = *(const float4*)&fp[0];
            float4 f1 = *(const float4*)&fp[4];
            float h;
            h = f2tf32(f0.x); s_Fh[j][ci+0] = h; s_Fl[j][ci+0] = f2tf32(f0.x - h);
            h = f2tf32(f0.y); s_Fh[j][ci+1] = h; s_Fl[j][ci+1] = f2tf32(f0.y - h);
            h = f2tf32(f0.z); s_Fh[j][ci+2] = h; s_Fl[j][ci+2] = f2tf32(f0.z - h);
            h = f2tf32(f0.w); s_Fh[j][ci+3] = h; s_Fl[j][ci+3] = f2tf32(f0.w - h);
            h = f2tf32(f1.x); s_Fh[j][ci+4] = h; s_Fl[j][ci+4] = f2tf32(f1.x - h);
            h = f2tf32(f1.y); s_Fh[j][ci+5] = h; s_Fl[j][ci+5] = f2tf32(f1.y - h);
            h = f2tf32(f1.z); s_Fh[j][ci+6] = h; s_Fl[j][ci+6] = f2tf32(f1.z - h);
            h = f2tf32(f1.w); s_Fh[j][ci+7] = h; s_Fl[j][ci+7] = f2tf32(f1.w - h);
        }
        // separable exp
        {
            int j = t >> 4, i2 = t & 15;
            float dx = ((float)(tx0 + i2) - s_px[j]) * s_isx[j];
            float dx2 = dx * dx;
            s_dx2[j][i2] = dx2;
            s_ex[j][i2] = __expf(-0.5f * dx2);
            float dy = ((float)(ty0 + i2) - s_py[j]) * s_isy[j];
            float dy2 = dy * dy;
            s_dy2[j][i2] = dy2;
            s_ey[j][i2] = __expf(-0.5f * dy2);
        }
        __syncthreads();
        // gw for my pixel across 16 gaussians (exact fp32 for density)
        #pragma unroll
        for (int j = 0; j < 16; j++) {
            float dd = s_dx2[j][lx] + s_dy2[j][ly];
            float gwv = (dd < 9.0f) ? s_w[j] * s_ex[j][lx] * s_ey[j][ly] : 0.0f;
            s_gwh[j][t] = f2tf32(gwv);
            dacc += gwv;
            uacc += gwv * s_as[j];
        }
        __syncthreads();
        // tensor-core accumulate: 2 ks x 4 mt x 8 nt x 2 splits
        #pragma unroll
        for (int ks = 0; ks < 2; ks++) {
            int kk = ks * 8;
            uint32_t ah[4][4], al[4][4];
            #pragma unroll
            for (int mt = 0; mt < 4; mt++) {
                int m = wm * 64 + mt * 16 + g;
                ah[mt][0] = __float_as_uint(s_Fh[kk + c][m]);
                ah[mt][1] = __float_as_uint(s_Fh[kk + c][m + 8]);
                ah[mt][2] = __float_as_uint(s_Fh[kk + c + 4][m]);
                ah[mt][3] = __float_as_uint(s_Fh[kk + c + 4][m + 8]);
                al[mt][0] = __float_as_uint(s_Fl[kk + c][m]);
                al[mt][1] = __float_as_uint(s_Fl[kk + c][m + 8]);
                al[mt][2] = __float_as_uint(s_Fl[kk + c + 4][m]);
                al[mt][3] = __float_as_uint(s_Fl[kk + c + 4][m + 8]);
            }
            #pragma unroll
            for (int nt = 0; nt < 8; nt++) {
                int n = wn * 64 + nt * 8 + g;
                uint32_t bh0 = __float_as_uint(s_gwh[kk + c][n]);
                uint32_t bh1 = __float_as_uint(s_gwh[kk + c + 4][n]);
                #pragma unroll
                for (int mt = 0; mt < 4; mt++) {
                    mma_tf32(d[mt][nt], ah[mt][0], ah[mt][1], ah[mt][2], ah[mt][3], bh0, bh1);
                    mma_tf32(d[mt][nt], al[mt][0], al[mt][1], al[mt][2], al[mt][3], bh0, bh1);
                }
            }
        }
        __syncthreads();
    }

    // density to smem (aliases s_dx2; safe after final sync)
    s_d[t] = dacc;
    __syncthreads();

    // normalize + write features
    #pragma unroll
    for (int nt = 0; nt < 8; nt++) {
        int n = wn * 64 + nt * 8 + c * 2;
        float inv0 = 1.0f / fmaxf(s_d[n], 1e-6f);
        float inv1 = 1.0f / fmaxf(s_d[n + 1], 1e-6f);
        int py = n >> 4;
        int pxx = n & 15;
        #pragma unroll
        for (int mt = 0; mt < 4; mt++) {
            int ch = slice * 128 + wm * 64 + mt * 16 + g;
            float* r0 = out + (((size_t)(b * CC + ch) * HI + ty0 + py) * WI + tx0 + pxx);
            float* r1 = out + (((size_t)(b * CC + ch + 8) * HI + ty0 + py) * WI + tx0 + pxx);
            *(float2*)r0 = make_float2(d[mt][nt][0] * inv0, d[mt][nt][1] * inv1);
            *(float2*)r1 = make_float2(d[mt][nt][2] * inv0, d[mt][nt][3] * inv1);
        }
    }
    if (slice == 0) {
        int pix = (ty0 + ly) * WI + tx0 + lx;
        float dv = fmaxf(dacc, 1e-6f);
        out[FM_SIZE + b * HW + pix] = uacc / dv;
        out[FM_SIZE + BB * HW + b * HW + pix] = dv;
    }
}

// ---------------- launch ----------------
extern "C" void kernel_launch(void* const* d_in, const int* in_sizes, int n_in,
                              void* d_out, int out_size) {
    const float* g      = (const float*)d_in[0];
    const float* intr   = (const float*)d_in[1];
    const float* enc_w1 = (const float*)d_in[2];
    const float* enc_b1 = (const float*)d_in[3];
    const float* enc_w2 = (const float*)d_in[4];
    const float* enc_b2 = (const float*)d_in[5];
    const float* enc_w3 = (const float*)d_in[6];
    const float* enc_b3 = (const float*)d_in[7];
    const float* ft_w1  = (const float*)d_in[8];
    const float* ft_b1  = (const float*)d_in[9];
    const float* ft_w2  = (const float*)d_in[10];
    const float* ft_b2  = (const float*)d_in[11];
    float* out = (float*)d_out;

    float *p_h1, *p_h2, *p_feats, *p_ft1, *p_featsT;
    int* p_tcount;
    cudaGetSymbolAddress((void**)&p_h1, g_h1);
    cudaGetSymbolAddress((void**)&p_h2, g_h2);
    cudaGetSymbolAddress((void**)&p_feats, g_feats);
    cudaGetSymbolAddress((void**)&p_ft1, g_ft1);
    cudaGetSymbolAddress((void**)&p_featsT, g_featsT);
    cudaGetSymbolAddress((void**)&p_tcount, g_tcount);

    cudaMemsetAsync(p_tcount, 0, NT * sizeof(int));
    proj_bin_kernel<<<(BN + 255) / 256, 256>>>(g, intr);

    gemm_tf32_kernel<<<dim3(BN / 64, 1), 256>>>(g,       enc_w1, enc_b1, p_h1,     14,  64,  1);
    gemm_tf32_kernel<<<dim3(BN / 64, 2), 256>>>(p_h1,    enc_w2, enc_b2, p_h2,     64,  128, 1);
    gemm_tf32_kernel<<<dim3(BN / 64, 4), 256>>>(p_h2,    enc_w3, enc_b3, p_feats,  128, 256, 0);
    gemm_tf32_kernel<<<dim3(BN / 64, 4), 256>>>(p_feats, ft_w1,  ft_b1,  p_ft1,    256, 256, 1);
    gemm_tf32_kernel<<<dim3(BN / 64, 4), 256>>>(p_ft1,   ft_w2,  ft_b2,  p_featsT, 256, 256, 0);

    render_kernel<<<dim3(NT, 2), 256>>>(out);
}

// round 13
// speedup vs baseline: 1.4465x; 1.4465x over previous
#include <cuda_runtime.h>
#include <cuda_bf16.h>
#include <math.h>
#include <stdint.h>

// Problem constants
#define BB 2
#define NN 2048
#define BN 4096          // B*N
#define CC 256
#define HI 64
#define WI 176
#define HW (HI*WI)       // 11264
#define TS 16            // tile size
#define TBX (WI/TS)      // 11
#define TBY (HI/TS)      // 4
#define TPB (TBX*TBY)    // 44 tiles per batch
#define NT (BB*TPB)      // 88 tiles total
#define MAXG 2048
#define FM_SIZE (BB*CC*HW)

// ---------------- device scratch ----------------
__device__ float g_h1[BN*64];
__device__ float g_h2[BN*128];
__device__ float g_feats[BN*CC];
__device__ float g_ft1[BN*CC];
__device__ float g_featsT[BN*CC];

__device__ float g_px[BN], g_py[BN], g_isx[BN], g_isy[BN], g_w[BN], g_as[BN];
__device__ int   g_tcount[NT];
__device__ int   g_tlist[NT*MAXG];

// ---------------- bf16 helpers ----------------
// split x into hi (bf16) + lo (bf16 of remainder); together ~16 mantissa bits
__device__ __forceinline__ void bfsplit(float x, __nv_bfloat16& h, __nv_bfloat16& l) {
    h = __float2bfloat16(x);
    l = __float2bfloat16(x - __bfloat162float(h));
}
// pack two bf16 (low half = first/even-k element)
__device__ __forceinline__ uint32_t pkbf(__nv_bfloat16 lo, __nv_bfloat16 hi) {
    __nv_bfloat162 v = __halves2bfloat162(lo, hi);
    return *(uint32_t*)&v;
}
__device__ __forceinline__ void mma_bf16(float* c,
    uint32_t a0, uint32_t a1, uint32_t a2, uint32_t a3,
    uint32_t b0, uint32_t b1)
{
    asm("mma.sync.aligned.m16n8k16.row.col.f32.bf16.bf16.f32 "
        "{%0,%1,%2,%3}, {%4,%5,%6,%7}, {%8,%9}, {%0,%1,%2,%3};"
        : "+f"(c[0]), "+f"(c[1]), "+f"(c[2]), "+f"(c[3])
        : "r"(a0), "r"(a1), "r"(a2), "r"(a3), "r"(b0), "r"(b1));
}

// ---------------- projection + binning (fused) ----------------
__global__ void proj_bin_kernel(const float* __restrict__ g, const float* __restrict__ Kin) {
    int i = blockIdx.x * blockDim.x + threadIdx.x;
    if (i >= BN) return;
    const float* gd = g + (size_t)i * 14;
    float x = gd[0], y = gd[1], z = gd[2];
    float k00 = Kin[0], k01 = Kin[1], k02 = Kin[2];
    float k10 = Kin[3], k11 = Kin[4], k12 = Kin[5];
    float k20 = Kin[6], k21 = Kin[7], k22 = Kin[8];
    float pz = k20 * x + k21 * y + k22 * z;
    float denom = pz + 1e-6f;
    float pxn = (k00 * x + k01 * y + k02 * z) / denom;
    float pyn = (k10 * x + k11 * y + k12 * z) / denom;
    float scale_x = (float)WI / k02 * 0.5f;
    float scale_y = (float)HI / k12 * 0.5f;
    float px = pxn * scale_x;
    float py = pyn * scale_y;
    bool valid = (z > 0.1f);
    bool inb = (px >= 0.f) && (px < (float)WI) && (py >= 0.f) && (py < (float)HI);
    bool mask = valid && inb;
    float sx = fmaxf(gd[5] * scale_x, 1.0f);
    float sy = fmaxf(gd[6] * scale_y, 1.0f);
    float w = mask ? gd[12] : 0.0f;
    g_px[i] = px;  g_py[i] = py;
    g_isx[i] = 1.0f / sx;  g_isy[i] = 1.0f / sy;
    g_w[i]  = w;
    g_as[i] = 0.5f * (sx + sy);
    if (w == 0.0f) return;

    float rx = 3.0f * sx;
    float ry = 3.0f * sy;
    int b = i >> 11;
    int tx0 = max(0, (int)floorf((px - rx) * (1.0f / TS)));
    int tx1 = min(TBX - 1, (int)floorf((px + rx) * (1.0f / TS)));
    int ty0 = max(0, (int)floorf((py - ry) * (1.0f / TS)));
    int ty1 = min(TBY - 1, (int)floorf((py + ry) * (1.0f / TS)));
    for (int ty = ty0; ty <= ty1; ty++)
        for (int tx = tx0; tx <= tx1; tx++) {
            int t = b * TPB + ty * TBX + tx;
            int o = atomicAdd(&g_tcount[t], 1);
            if (o < MAXG) g_tlist[t * MAXG + o] = i;
        }
}

// ---------------- bf16 GEMM: 64x64 tile, double-buffered, 2-split bf16 -------
// C = act(A @ W + b). 256 threads = 8 warps (2M x 4N), warp tile 32x16.
// Per 16-k slab and (mt,nt): 3x mma.m16n8k16 (ah*bh + al*bh + ah*bl).
// smem holds bf16 PAIRS along k: [k2][m] with k2 = k/2; pads ≡8 mod 32.
__global__ void __launch_bounds__(256) gemm_bf16_kernel(
    const float* __restrict__ A, const float* __restrict__ Wm,
    const float* __restrict__ bias, float* __restrict__ Cm,
    int Kd, int Nd, int doRelu)
{
    __shared__ uint32_t Ahp[2][8][136], Alp[2][8][136];   // [buf][k2][m]
    __shared__ uint32_t Bhp[2][8][72],  Blp[2][8][72];    // [buf][k2][n]

    int m0 = blockIdx.x * 64;
    int n0 = blockIdx.y * 64;
    int t = threadIdx.x;
    int lane = t & 31;
    int wid = t >> 5;
    int wm = wid & 1;
    int wn = wid >> 1;
    int g = lane >> 2;
    int c = lane & 3;

    float d[2][2][4];
    #pragma unroll
    for (int mt = 0; mt < 2; mt++)
        #pragma unroll
        for (int nt = 0; nt < 2; nt++)
            #pragma unroll
            for (int i = 0; i < 4; i++) d[mt][nt][i] = 0.f;

    int nkt = (Kd + 15) >> 4;
    bool fast = ((Kd & 15) == 0);

    int arow = t >> 2, ak0 = (t & 3) * 4;     // A: row, 4 consecutive k
    int bk2 = t >> 5, bn2 = (t & 31) * 2;     // B: k-pair index, 2 cols

    float av[4];
    float2 bv0, bv1;
    // prefetch k-tile 0
    if (fast) {
        float4 q = *(const float4*)&A[(size_t)(m0 + arow) * Kd + ak0];
        av[0]=q.x; av[1]=q.y; av[2]=q.z; av[3]=q.w;
        bv0 = *(const float2*)&Wm[(size_t)(2*bk2) * Nd + n0 + bn2];
        bv1 = *(const float2*)&Wm[(size_t)(2*bk2+1) * Nd + n0 + bn2];
    } else {
        #pragma unroll
        for (int i = 0; i < 4; i++)
            av[i] = (ak0 + i < Kd) ? A[(size_t)(m0 + arow) * Kd + ak0 + i] : 0.f;
        bv0 = (2*bk2   < Kd) ? *(const float2*)&Wm[(size_t)(2*bk2)   * Nd + n0 + bn2] : make_float2(0.f,0.f);
        bv1 = (2*bk2+1 < Kd) ? *(const float2*)&Wm[(size_t)(2*bk2+1) * Nd + n0 + bn2] : make_float2(0.f,0.f);
    }

    for (int kt = 0; kt < nkt; kt++) {
        int buf = kt & 1;
        // split + pack + store
        {
            __nv_bfloat16 h0,l0,h1,l1,h2,l2,h3,l3;
            bfsplit(av[0], h0, l0); bfsplit(av[1], h1, l1);
            bfsplit(av[2], h2, l2); bfsplit(av[3], h3, l3);
            int k2 = ak0 >> 1;
            Ahp[buf][k2][arow]   = pkbf(h0, h1);
            Alp[buf][k2][arow]   = pkbf(l0, l1);
            Ahp[buf][k2+1][arow] = pkbf(h2, h3);
            Alp[buf][k2+1][arow] = pkbf(l2, l3);
        }
        {
            __nv_bfloat16 he0,le0,ho0,lo0, he1,le1,ho1,lo1;
            bfsplit(bv0.x, he0, le0); bfsplit(bv1.x, ho0, lo0);
            bfsplit(bv0.y, he1, le1); bfsplit(bv1.y, ho1, lo1);
            Bhp[buf][bk2][bn2]   = pkbf(he0, ho0);   // (k even, k odd) for col bn2
            Blp[buf][bk2][bn2]   = pkbf(le0, lo0);
            Bhp[buf][bk2][bn2+1] = pkbf(he1, ho1);
            Blp[buf][bk2][bn2+1] = pkbf(le1, lo1);
        }
        __syncthreads();
        // prefetch next k-tile (overlaps mma)
        if (kt + 1 < nkt) {
            int kb = (kt + 1) * 16;
            if (fast) {
                float4 q = *(const float4*)&A[(size_t)(m0 + arow) * Kd + kb + ak0];
                av[0]=q.x; av[1]=q.y; av[2]=q.z; av[3]=q.w;
                bv0 = *(const float2*)&Wm[(size_t)(kb + 2*bk2) * Nd + n0 + bn2];
                bv1 = *(const float2*)&Wm[(size_t)(kb + 2*bk2+1) * Nd + n0 + bn2];
            } else {
                #pragma unroll
                for (int i = 0; i < 4; i++)
                    av[i] = (kb + ak0 + i < Kd) ? A[(size_t)(m0 + arow) * Kd + kb + ak0 + i] : 0.f;
                bv0 = (kb + 2*bk2   < Kd) ? *(const float2*)&Wm[(size_t)(kb + 2*bk2)   * Nd + n0 + bn2] : make_float2(0.f,0.f);
                bv1 = (kb + 2*bk2+1 < Kd) ? *(const float2*)&Wm[(size_t)(kb + 2*bk2+1) * Nd + n0 + bn2] : make_float2(0.f,0.f);
            }
        }
        // one k16 mma step
        {
            uint32_t ah[2][4], al[2][4], bh[2][2], bl[2][2];
            #pragma unroll
            for (int mt = 0; mt < 2; mt++) {
                int m = wm * 32 + mt * 16 + g;
                ah[mt][0] = Ahp[buf][c][m];     ah[mt][1] = Ahp[buf][c][m + 8];
                ah[mt][2] = Ahp[buf][c+4][m];   ah[mt][3] = Ahp[buf][c+4][m + 8];
                al[mt][0] = Alp[buf][c][m];     al[mt][1] = Alp[buf][c][m + 8];
                al[mt][2] = Alp[buf][c+4][m];   al[mt][3] = Alp[buf][c+4][m + 8];
            }
            #pragma unroll
            for (int nt = 0; nt < 2; nt++) {
                int n = wn * 16 + nt * 8 + g;
                bh[nt][0] = Bhp[buf][c][n];     bh[nt][1] = Bhp[buf][c+4][n];
                bl[nt][0] = Blp[buf][c][n];     bl[nt][1] = Blp[buf][c+4][n];
            }
            #pragma unroll
            for (int mt = 0; mt < 2; mt++)
                #pragma unroll
                for (int nt = 0; nt < 2; nt++) {
                    mma_bf16(d[mt][nt], ah[mt][0], ah[mt][1], ah[mt][2], ah[mt][3],
                             bh[nt][0], bh[nt][1]);
                    mma_bf16(d[mt][nt], al[mt][0], al[mt][1], al[mt][2], al[mt][3],
                             bh[nt][0], bh[nt][1]);
                    mma_bf16(d[mt][nt], ah[mt][0], ah[mt][1], ah[mt][2], ah[mt][3],
                             bl[nt][0], bl[nt][1]);
                }
        }
        __syncthreads();
    }

    // epilogue (D layout: rows g,g+8; cols 2c,2c+1)
    #pragma unroll
    for (int nt = 0; nt < 2; nt++) {
        int col = n0 + wn * 16 + nt * 8 + c * 2;
        float2 bv2 = *(const float2*)&bias[col];
        #pragma unroll
        for (int mt = 0; mt < 2; mt++) {
            int row0 = m0 + wm * 32 + mt * 16 + g;
            float2 o0 = make_float2(d[mt][nt][0] + bv2.x, d[mt][nt][1] + bv2.y);
            float2 o1 = make_float2(d[mt][nt][2] + bv2.x, d[mt][nt][3] + bv2.y);
            if (doRelu) {
                o0.x = fmaxf(o0.x, 0.f); o0.y = fmaxf(o0.y, 0.f);
                o1.x = fmaxf(o1.x, 0.f); o1.y = fmaxf(o1.y, 0.f);
            }
            *(float2*)&Cm[(size_t)row0 * Nd + col]       = o0;
            *(float2*)&Cm[(size_t)(row0 + 8) * Nd + col] = o1;
        }
    }
}

// ---------------- tile render: 4 slices x 64 ch, bf16 2-split MMA -------------
// grid (NT, 4), 256 threads = 8 warps in 2(ch: 32 each) x 4(px: 64 each).
// Per 16-gaussian batch: one k16 slab, 3 MMAs per (mt,nt).
__global__ void __launch_bounds__(256, 2) render_kernel(float* __restrict__ out) {
    int tile = blockIdx.x;
    int slice = blockIdx.y;
    int b = tile / TPB;
    int tl = tile % TPB;
    int tx0 = (tl % TBX) * TS;
    int ty0 = (tl / TBX) * TS;
    int t = threadIdx.x;
    int lx = t & 15;
    int ly = t >> 4;
    int lane = t & 31;
    int wid = t >> 5;
    int wm = wid & 1;        // 2 warps in channels (32 each)
    int wn = wid >> 1;       // 4 warps in pixels (64 each)
    int g = lane >> 2;
    int c = lane & 3;

    __shared__ float s_px[16], s_py[16], s_isx[16], s_isy[16], s_w[16], s_as[16];
    __shared__ int   s_n[16];
    __shared__ float s_dx2[16][16], s_dy2[16][16], s_ex[16][16], s_ey[16][16];
    __shared__ uint32_t s_gwh[8][264], s_gwl[8][264];   // [j2][pixel] bf16 pairs
    __shared__ uint32_t s_Fh[8][136], s_Fl[8][136];     // [j2][ch] pairs (64ch + pad)

    float* s_d = &s_dx2[0][0];   // reused for density after main loop

    float d[2][8][4];
    #pragma unroll
    for (int mt = 0; mt < 2; mt++)
        #pragma unroll
        for (int nt = 0; nt < 8; nt++)
            #pragma unroll
            for (int i = 0; i < 4; i++) d[mt][nt][i] = 0.f;
    float dacc = 0.f, uacc = 0.f;

    int K = g_tcount[tile];
    if (K > MAXG) K = MAXG;

    for (int c0 = 0; c0 < K; c0 += 16) {
        if (t < 16) {
            int idx = c0 + t;
            if (idx < K) {
                int n = g_tlist[tile * MAXG + idx];
                s_n[t] = n;
                s_px[t] = g_px[n];   s_py[t] = g_py[n];
                s_isx[t] = g_isx[n]; s_isy[t] = g_isy[n];
                s_w[t] = g_w[n];     s_as[t] = g_as[n];
            } else {
                s_n[t] = 0;
                s_px[t] = 3e8f; s_py[t] = 3e8f;
                s_isx[t] = 1.f; s_isy[t] = 1.f;
                s_w[t] = 0.f;   s_as[t] = 0.f;
            }
        }
        __syncthreads();
        // F slice: 16 gaussians x 64 channels -> bf16 pairs along j.
        // 256 threads: j2 = t>>5 (0..7), ch2 = (t&31)*2 (2 channels each).
        {
            int j2 = t >> 5;
            int ch2 = (t & 31) * 2;
            int ne = s_n[2 * j2], no = s_n[2 * j2 + 1];
            float2 fe = *(const float2*)&g_featsT[(size_t)ne * CC + slice * 64 + ch2];
            float2 fo = *(const float2*)&g_featsT[(size_t)no * CC + slice * 64 + ch2];
            __nv_bfloat16 he,le,ho,lo;
            bfsplit(fe.x, he, le); bfsplit(fo.x, ho, lo);
            s_Fh[j2][ch2]   = pkbf(he, ho);
            s_Fl[j2][ch2]   = pkbf(le, lo);
            bfsplit(fe.y, he, le); bfsplit(fo.y, ho, lo);
            s_Fh[j2][ch2+1] = pkbf(he, ho);
            s_Fl[j2][ch2+1] = pkbf(le, lo);
        }
        // separable exp
        {
            int j = t >> 4, i2 = t & 15;
            float dx = ((float)(tx0 + i2) - s_px[j]) * s_isx[j];
            float dx2 = dx * dx;
            s_dx2[j][i2] = dx2;
            s_ex[j][i2] = __expf(-0.5f * dx2);
            float dy = ((float)(ty0 + i2) - s_py[j]) * s_isy[j];
            float dy2 = dy * dy;
            s_dy2[j][i2] = dy2;
            s_ey[j][i2] = __expf(-0.5f * dy2);
        }
        __syncthreads();
        // gw for my pixel across 16 gaussians (exact fp32 density), pack bf16 pairs
        #pragma unroll
        for (int j2 = 0; j2 < 8; j2++) {
            int j0 = 2 * j2, j1 = 2 * j2 + 1;
            float dd0 = s_dx2[j0][lx] + s_dy2[j0][ly];
            float dd1 = s_dx2[j1][lx] + s_dy2[j1][ly];
            float g0 = (dd0 < 9.0f) ? s_w[j0] * s_ex[j0][lx] * s_ey[j0][ly] : 0.0f;
            float g1 = (dd1 < 9.0f) ? s_w[j1] * s_ex[j1][lx] * s_ey[j1][ly] : 0.0f;
            dacc += g0 + g1;
            uacc += g0 * s_as[j0] + g1 * s_as[j1];
            __nv_bfloat16 h0,l0,h1,l1;
            bfsplit(g0, h0, l0); bfsplit(g1, h1, l1);
            s_gwh[j2][t] = pkbf(h0, h1);
            s_gwl[j2][t] = pkbf(l0, l1);
        }
        __syncthreads();
        // one k16 mma slab: 2 mt x 8 nt x 3 terms
        {
            uint32_t ah[2][4], al[2][4];
            #pragma unroll
            for (int mt = 0; mt < 2; mt++) {
                int m = wm * 32 + mt * 16 + g;
                ah[mt][0] = s_Fh[c][m];     ah[mt][1] = s_Fh[c][m + 8];
                ah[mt][2] = s_Fh[c+4][m];   ah[mt][3] = s_Fh[c+4][m + 8];
                al[mt][0] = s_Fl[c][m];     al[mt][1] = s_Fl[c][m + 8];
                al[mt][2] = s_Fl[c+4][m];   al[mt][3] = s_Fl[c+4][m + 8];
            }
            #pragma unroll
            for (int nt = 0; nt < 8; nt++) {
                int n = wn * 64 + nt * 8 + g;
                uint32_t bh0 = s_gwh[c][n],   bh1 = s_gwh[c+4][n];
                uint32_t bl0 = s_gwl[c][n],   bl1 = s_gwl[c+4][n];
                #pragma unroll
                for (int mt = 0; mt < 2; mt++) {
                    mma_bf16(d[mt][nt], ah[mt][0], ah[mt][1], ah[mt][2], ah[mt][3], bh0, bh1);
                    mma_bf16(d[mt][nt], al[mt][0], al[mt][1], al[mt][2], al[mt][3], bh0, bh1);
                    mma_bf16(d[mt][nt], ah[mt][0], ah[mt][1], ah[mt][2], ah[mt][3], bl0, bl1);
                }
            }
        }
        __syncthreads();
    }

    // density to smem (aliases s_dx2; safe after final sync)
    s_d[t] = dacc;
    __syncthreads();

    // normalize + write features
    #pragma unroll
    for (int nt = 0; nt < 8; nt++) {
        int n = wn * 64 + nt * 8 + c * 2;
        float inv0 = 1.0f / fmaxf(s_d[n], 1e-6f);
        float inv1 = 1.0f / fmaxf(s_d[n + 1], 1e-6f);
        int py = n >> 4;
        int pxx = n & 15;
        #pragma unroll
        for (int mt = 0; mt < 2; mt++) {
            int ch = slice * 64 + wm * 32 + mt * 16 + g;
            float* r0 = out + (((size_t)(b * CC + ch) * HI + ty0 + py) * WI + tx0 + pxx);
            float* r1 = out + (((size_t)(b * CC + ch + 8) * HI + ty0 + py) * WI + tx0 + pxx);
            *(float2*)r0 = make_float2(d[mt][nt][0] * inv0, d[mt][nt][1] * inv1);
            *(float2*)r1 = make_float2(d[mt][nt][2] * inv0, d[mt][nt][3] * inv1);
        }
    }
    if (slice == 0) {
        int pix = (ty0 + ly) * WI + tx0 + lx;
        float dv = fmaxf(dacc, 1e-6f);
        out[FM_SIZE + b * HW + pix] = uacc / dv;
        out[FM_SIZE + BB * HW + b * HW + pix] = dv;
    }
}

// ---------------- launch ----------------
extern "C" void kernel_launch(void* const* d_in, const int* in_sizes, int n_in,
                              void* d_out, int out_size) {
    const float* g      = (const float*)d_in[0];
    const float* intr   = (const float*)d_in[1];
    const float* enc_w1 = (const float*)d_in[2];
    const float* enc_b1 = (const float*)d_in[3];
    const float* enc_w2 = (const float*)d_in[4];
    const float* enc_b2 = (const float*)d_in[5];
    const float* enc_w3 = (const float*)d_in[6];
    const float* enc_b3 = (const float*)d_in[7];
    const float* ft_w1  = (const float*)d_in[8];
    const float* ft_b1  = (const float*)d_in[9];
    const float* ft_w2  = (const float*)d_in[10];
    const float* ft_b2  = (const float*)d_in[11];
    float* out = (float*)d_out;

    float *p_h1, *p_h2, *p_feats, *p_ft1, *p_featsT;
    int* p_tcount;
    cudaGetSymbolAddress((void**)&p_h1, g_h1);
    cudaGetSymbolAddress((void**)&p_h2, g_h2);
    cudaGetSymbolAddress((void**)&p_feats, g_feats);
    cudaGetSymbolAddress((void**)&p_ft1, g_ft1);
    cudaGetSymbolAddress((void**)&p_featsT, g_featsT);
    cudaGetSymbolAddress((void**)&p_tcount, g_tcount);

    cudaMemsetAsync(p_tcount, 0, NT * sizeof(int));
    proj_bin_kernel<<<(BN + 255) / 256, 256>>>(g, intr);

    gemm_bf16_kernel<<<dim3(BN / 64, 1), 256>>>(g,       enc_w1, enc_b1, p_h1,     14,  64,  1);
    gemm_bf16_kernel<<<dim3(BN / 64, 2), 256>>>(p_h1,    enc_w2, enc_b2, p_h2,     64,  128, 1);
    gemm_bf16_kernel<<<dim3(BN / 64, 4), 256>>>(p_h2,    enc_w3, enc_b3, p_feats,  128, 256, 0);
    gemm_bf16_kernel<<<dim3(BN / 64, 4), 256>>>(p_feats, ft_w1,  ft_b1,  p_ft1,    256, 256, 1);
    gemm_bf16_kernel<<<dim3(BN / 64, 4), 256>>>(p_ft1,   ft_w2,  ft_b2,  p_featsT, 256, 256, 0);

    render_kernel<<<dim3(NT, 4), 256>>>(out);
}